// round 7
// baseline (speedup 1.0000x reference)
#include <cuda_runtime.h>

#define M_ROWS 25088
#define C_IN   768
#define DIM    64
#define NE     8192

typedef unsigned long long u64;

// ---------------- scratch (device globals; no allocations allowed) ------------
__device__ float g_zf [M_ROWS * DIM];     // compressed rows, row-major (loss kernel)
__device__ float g_zfT[DIM * M_ROWS];     // compressed rows, K-major (argmax GEMM)
__device__ float g_embT[DIM * NE];        // emb transposed, K-major
__device__ float g_WeT [DIM * C_IN];      // We transposed, K-major
__device__ int   g_idx [M_ROWS];
__device__ float g_partial[M_ROWS / 8];   // per-block loss partials
__device__ float g_bv[2 * M_ROWS];        // per-n-half best value
__device__ int   g_bi[2 * M_ROWS];        // per-n-half best index

// packed f32x2 FMA (sm_103a FFMA2 — 2 fp32 MACs per fma-pipe slot)
#define FMA2(acc, a, b) asm("fma.rn.f32x2 %0, %1, %2, %0;" : "+l"(acc) : "l"(a), "l"(b))
#define BCAST2(dst, f)  asm("mov.b64 %0, {%1, %1};"        : "=l"(dst) : "f"(f))

__device__ __forceinline__ float lo32(u64 v) { return __uint_as_float((unsigned)(v)); }
__device__ __forceinline__ float hi32(u64 v) { return __uint_as_float((unsigned)(v >> 32)); }

// ---------------- 0) transpose emb and We into K-major scratch ----------------
__global__ void k_transpose(const float* __restrict__ emb, const float* __restrict__ We) {
    int i = blockIdx.x * 256 + threadIdx.x;
    if (i < NE * DIM)   { int n = i >> 6, k = i & 63; g_embT[k * NE   + n] = emb[i]; }
    if (i < C_IN * DIM) { int c = i >> 6, k = i & 63; g_WeT [k * C_IN + c] = We[i];  }
}

// ---------------- 1) compress: zf[m,d] = sum_c z[m,c]*Wc[d,c] + bc[d] ---------
__global__ __launch_bounds__(256) void k_compress(const float* __restrict__ z,
                                                  const float* __restrict__ Wc,
                                                  const float* __restrict__ bc) {
    __shared__ __align__(16) float As[32][68];   // As[k][m] (K-major)
    __shared__ __align__(16) float Bs[32][68];   // Bs[k][d]
    const int m0 = blockIdx.x * 64;
    const int tx = threadIdx.x & 15;
    const int ty = threadIdx.x >> 4;

    u64 acc[2][4];
#pragma unroll
    for (int i = 0; i < 2; i++)
#pragma unroll
        for (int j = 0; j < 4; j++) acc[i][j] = 0ull;

    for (int kk = 0; kk < C_IN; kk += 32) {
#pragma unroll
        for (int i = threadIdx.x; i < 64 * 32; i += 256) {
            int m = i >> 5, k = i & 31;
            As[k][m] = z[(size_t)(m0 + m) * C_IN + kk + k];
        }
#pragma unroll
        for (int i = threadIdx.x; i < 64 * 32; i += 256) {
            int n = i >> 5, k = i & 31;
            Bs[k][n] = Wc[(size_t)n * C_IN + kk + k];
        }
        __syncthreads();
#pragma unroll 8
        for (int k = 0; k < 32; k++) {
            ulonglong2 A = *reinterpret_cast<const ulonglong2*>(&As[k][ty * 4]);
            float4 bv = *reinterpret_cast<const float4*>(&Bs[k][tx * 4]);
            u64 b0, b1, b2, b3;
            BCAST2(b0, bv.x); BCAST2(b1, bv.y); BCAST2(b2, bv.z); BCAST2(b3, bv.w);
            FMA2(acc[0][0], A.x, b0); FMA2(acc[0][1], A.x, b1);
            FMA2(acc[0][2], A.x, b2); FMA2(acc[0][3], A.x, b3);
            FMA2(acc[1][0], A.y, b0); FMA2(acc[1][1], A.y, b1);
            FMA2(acc[1][2], A.y, b2); FMA2(acc[1][3], A.y, b3);
        }
        __syncthreads();
    }
#pragma unroll
    for (int i2 = 0; i2 < 2; i2++)
#pragma unroll
        for (int h = 0; h < 2; h++) {
            int m = m0 + ty * 4 + i2 * 2 + h;
#pragma unroll
            for (int j = 0; j < 4; j++) {
                int d = tx * 4 + j;
                float v = (h ? hi32(acc[i2][j]) : lo32(acc[i2][j])) + bc[d];
                g_zf [(size_t)m * DIM + d]    = v;
                g_zfT[(size_t)d * M_ROWS + m] = v;
            }
        }
}

// ------- 2) fused sim GEMM + argmax over one n-half --------------------------
// grid = 784: blockIdx = mtile*2 + half. Tile: 64 m x 128 n inner, K=64 resident.
// Thread tile: 4 m (scalar, broadcast) x 8 n (packed f32x2 pairs).
// Next Es tile is prefetched into registers (plain LDG) while computing the
// current tile, then stored to smem after the post-compute barrier.
__global__ __launch_bounds__(256) void k_argmax() {
    __shared__ __align__(16) float Zs[64][68];    // Zs[k][m]
    __shared__ __align__(16) float Es[64][132];   // Es[k][n] (128 cols + pad)
    __shared__ float red_v[64][17];
    __shared__ int   red_i[64][17];

    const int tid  = threadIdx.x;
    const int bid  = blockIdx.x;
    const int m0   = (bid >> 1) * 64;
    const int half = bid & 1;
    const int nbase = half * (NE / 2);
    const int tx = tid & 15;
    const int ty = tid >> 4;

    // per-thread (k,q) slots for the Es tile (8 float4 each, fixed across tiles)
    int sk[8], sq[8];
#pragma unroll
    for (int j = 0; j < 8; j++) {
        int i = tid + j * 256;
        sk[j] = i >> 5; sq[j] = (i & 31) * 4;
    }

    // load Zs (64k x 64m), K-major source: fully coalesced
#pragma unroll
    for (int i = tid; i < 64 * 16; i += 256) {
        int k = i >> 4, q = i & 15;
        *reinterpret_cast<float4*>(&Zs[k][q * 4]) =
            *reinterpret_cast<const float4*>(&g_zfT[(size_t)k * M_ROWS + m0 + q * 4]);
    }
    // preload Es tile 0 straight to smem
#pragma unroll
    for (int j = 0; j < 8; j++) {
        *reinterpret_cast<float4*>(&Es[sk[j]][sq[j]]) =
            *reinterpret_cast<const float4*>(&g_embT[(size_t)sk[j] * NE + nbase + sq[j]]);
    }

    float best[4]; int bidx[4];
#pragma unroll
    for (int i = 0; i < 4; i++) { best[i] = -3.0e38f; bidx[i] = 0; }
    __syncthreads();

    const int NT = (NE / 2) / 128;   // 32 tiles
    for (int t = 0; t < NT; t++) {
        // issue LDGs for next tile into registers (overlaps with compute below)
        float4 stage[8];
        if (t + 1 < NT) {
            const int nb = nbase + (t + 1) * 128;
#pragma unroll
            for (int j = 0; j < 8; j++)
                stage[j] = *reinterpret_cast<const float4*>(
                    &g_embT[(size_t)sk[j] * NE + nb + sq[j]]);
        }

        u64 acc[4][4];   // acc[i][p]: m = ty*4+i, n-pair p (lo=even n, hi=odd n)
#pragma unroll
        for (int i = 0; i < 4; i++)
#pragma unroll
            for (int p = 0; p < 4; p++) acc[i][p] = 0ull;

#pragma unroll 8
        for (int k = 0; k < 64; k++) {
            float4 av = *reinterpret_cast<const float4*>(&Zs[k][ty * 4]);
            ulonglong2 B0 = *reinterpret_cast<const ulonglong2*>(&Es[k][tx * 4]);
            ulonglong2 B1 = *reinterpret_cast<const ulonglong2*>(&Es[k][64 + tx * 4]);
            u64 a0, a1, a2, a3;
            BCAST2(a0, av.x); BCAST2(a1, av.y); BCAST2(a2, av.z); BCAST2(a3, av.w);
            FMA2(acc[0][0], a0, B0.x); FMA2(acc[0][1], a0, B0.y);
            FMA2(acc[0][2], a0, B1.x); FMA2(acc[0][3], a0, B1.y);
            FMA2(acc[1][0], a1, B0.x); FMA2(acc[1][1], a1, B0.y);
            FMA2(acc[1][2], a1, B1.x); FMA2(acc[1][3], a1, B1.y);
            FMA2(acc[2][0], a2, B0.x); FMA2(acc[2][1], a2, B0.y);
            FMA2(acc[2][2], a2, B1.x); FMA2(acc[2][3], a2, B1.y);
            FMA2(acc[3][0], a3, B0.x); FMA2(acc[3][1], a3, B0.y);
            FMA2(acc[3][2], a3, B1.x); FMA2(acc[3][3], a3, B1.y);
        }

        // argmax update: scan n ascending per m-row; strict '>' keeps first index
        const int nt0 = nbase + t * 128;
#pragma unroll
        for (int i = 0; i < 4; i++) {
#pragma unroll
            for (int p = 0; p < 4; p++) {
                int n = nt0 + ((p < 2) ? (tx * 4 + p * 2) : (64 + tx * 4 + (p - 2) * 2));
                float vlo = lo32(acc[i][p]), vhi = hi32(acc[i][p]);
                if (vlo > best[i]) { best[i] = vlo; bidx[i] = n; }
                if (vhi > best[i]) { best[i] = vhi; bidx[i] = n + 1; }
            }
        }
        __syncthreads();   // all warps done reading Es
        if (t + 1 < NT) {
#pragma unroll
            for (int j = 0; j < 8; j++)
                *reinterpret_cast<float4*>(&Es[sk[j]][sq[j]]) = stage[j];
        }
        __syncthreads();   // Es refilled for next iteration
    }

    // cross-tx reduction per m row
#pragma unroll
    for (int i = 0; i < 4; i++) {
        red_v[ty * 4 + i][tx] = best[i];
        red_i[ty * 4 + i][tx] = bidx[i];
    }
    __syncthreads();
    if (tid < 64) {
        int m = tid;
        float bv = red_v[m][0]; int bi = red_i[m][0];
#pragma unroll
        for (int t = 1; t < 16; t++) {
            float v = red_v[m][t]; int id = red_i[m][t];
            if (v > bv || (v == bv && id < bi)) { bv = v; bi = id; }
        }
        g_bv[half * M_ROWS + m0 + m] = bv;
        g_bi[half * M_ROWS + m0 + m] = bi;
    }
}

// ------- 2b) merge the two n-halves; tie -> lower index (= half 0) -----------
__global__ void k_merge() {
    int m = blockIdx.x * 256 + threadIdx.x;
    if (m < M_ROWS) {
        float v0 = g_bv[m], v1 = g_bv[M_ROWS + m];
        g_idx[m] = (v1 > v0) ? g_bi[M_ROWS + m] : g_bi[m];
    }
}

// ------- 3) expand: out[m,c] = sum_d emb[idx[m],d]*We[c,d] + be[c] -----------
__global__ __launch_bounds__(256) void k_expand(const float* __restrict__ emb,
                                                const float* __restrict__ be,
                                                float* __restrict__ out) {
    __shared__ __align__(16) float Zq[64][68];   // Zq[k][m] (gathered, K-major)
    __shared__ __align__(16) float Ws[64][68];   // Ws[k][c]
    const int m0 = blockIdx.x * 64;
    const int tx = threadIdx.x & 15;
    const int ty = threadIdx.x >> 4;

#pragma unroll
    for (int i = threadIdx.x; i < 64 * 16; i += 256) {
        int m = i >> 4, q = i & 15;
        float4 v = *reinterpret_cast<const float4*>(&emb[(size_t)g_idx[m0 + m] * DIM + q * 4]);
        Zq[q * 4 + 0][m] = v.x; Zq[q * 4 + 1][m] = v.y;
        Zq[q * 4 + 2][m] = v.z; Zq[q * 4 + 3][m] = v.w;
    }
    __syncthreads();

    for (int n0 = 0; n0 < C_IN; n0 += 64) {
#pragma unroll
        for (int i = threadIdx.x; i < 64 * 16; i += 256) {
            int k = i >> 4, q = i & 15;
            *reinterpret_cast<float4*>(&Ws[k][q * 4]) =
                *reinterpret_cast<const float4*>(&g_WeT[(size_t)k * C_IN + n0 + q * 4]);
        }
        __syncthreads();

        u64 acc[2][4];
#pragma unroll
        for (int i = 0; i < 2; i++)
#pragma unroll
            for (int j = 0; j < 4; j++) acc[i][j] = 0ull;

#pragma unroll 8
        for (int k = 0; k < 64; k++) {
            ulonglong2 A = *reinterpret_cast<const ulonglong2*>(&Zq[k][ty * 4]);
            float4 bv = *reinterpret_cast<const float4*>(&Ws[k][tx * 4]);
            u64 b0, b1, b2, b3;
            BCAST2(b0, bv.x); BCAST2(b1, bv.y); BCAST2(b2, bv.z); BCAST2(b3, bv.w);
            FMA2(acc[0][0], A.x, b0); FMA2(acc[0][1], A.x, b1);
            FMA2(acc[0][2], A.x, b2); FMA2(acc[0][3], A.x, b3);
            FMA2(acc[1][0], A.y, b0); FMA2(acc[1][1], A.y, b1);
            FMA2(acc[1][2], A.y, b2); FMA2(acc[1][3], A.y, b3);
        }

        float4 bev = *reinterpret_cast<const float4*>(&be[n0 + tx * 4]);
#pragma unroll
        for (int i2 = 0; i2 < 2; i2++)
#pragma unroll
            for (int h = 0; h < 2; h++) {
                int m = m0 + ty * 4 + i2 * 2 + h;
                float4 o;
                o.x = (h ? hi32(acc[i2][0]) : lo32(acc[i2][0])) + bev.x;
                o.y = (h ? hi32(acc[i2][1]) : lo32(acc[i2][1])) + bev.y;
                o.z = (h ? hi32(acc[i2][2]) : lo32(acc[i2][2])) + bev.z;
                o.w = (h ? hi32(acc[i2][3]) : lo32(acc[i2][3])) + bev.w;
                *reinterpret_cast<float4*>(&out[(size_t)m * C_IN + n0 + tx * 4]) = o;
            }
        __syncthreads();
    }
}

// ------- 4) loss partials: one warp per row, deterministic reduction ---------
__global__ void k_loss(const float* __restrict__ emb) {
    int t = blockIdx.x * 256 + threadIdx.x;
    int row = t >> 5;
    int lane = t & 31;
    const float* a = g_zf + (size_t)row * DIM;
    const float* b = emb + (size_t)g_idx[row] * DIM;
    float d = 0.f, na = 0.f, nb = 0.f;
#pragma unroll
    for (int q = 0; q < 2; q++) {
        float x = a[lane + 32 * q], y = b[lane + 32 * q];
        d = fmaf(x, y, d); na = fmaf(x, x, na); nb = fmaf(y, y, nb);
    }
#pragma unroll
    for (int o = 16; o; o >>= 1) {
        d  += __shfl_xor_sync(0xffffffffu, d, o);
        na += __shfl_xor_sync(0xffffffffu, na, o);
        nb += __shfl_xor_sync(0xffffffffu, nb, o);
    }
    __shared__ float s[8];
    if (lane == 0)
        s[threadIdx.x >> 5] = 1.0f - d / (fmaxf(sqrtf(na), 1e-8f) * fmaxf(sqrtf(nb), 1e-8f));
    __syncthreads();
    if (threadIdx.x == 0) {
        float sum = 0.f;
#pragma unroll
        for (int w = 0; w < 8; w++) sum += s[w];
        g_partial[blockIdx.x] = sum;
    }
}

// ------- 5) finalize loss: loss = 3 * mean(1 - cos) --------------------------
__global__ void k_finalize(float* __restrict__ out, int out_size) {
    __shared__ float s[256];
    float sum = 0.f;
    for (int i = threadIdx.x; i < M_ROWS / 8; i += 256) sum += g_partial[i];
    s[threadIdx.x] = sum;
    __syncthreads();
    for (int o = 128; o; o >>= 1) {
        if (threadIdx.x < o) s[threadIdx.x] += s[threadIdx.x + o];
        __syncthreads();
    }
    if (threadIdx.x == 0 && out_size > M_ROWS * C_IN)
        out[M_ROWS * C_IN] = 3.0f * s[0] / (float)M_ROWS;
}

// -----------------------------------------------------------------------------
extern "C" void kernel_launch(void* const* d_in, const int* in_sizes, int n_in,
                              void* d_out, int out_size) {
    const float *z = nullptr, *emb = nullptr, *Wc = nullptr, *bc = nullptr,
                *We = nullptr, *be = nullptr;
    for (int i = 0; i < n_in; i++) {
        int s = in_sizes[i];
        const float* p = (const float*)d_in[i];
        if      (s == M_ROWS * C_IN) z = p;
        else if (s == NE * DIM)      emb = p;
        else if (s == DIM)           bc = p;
        else if (s == C_IN)          be = p;
        else if (s == DIM * C_IN)    { if (!Wc) Wc = p; else We = p; }  // setup order: Wc then We
    }
    float* out = (float*)d_out;

    k_transpose<<<(NE * DIM + 255) / 256, 256>>>(emb, We);
    k_compress <<<M_ROWS / 64, 256>>>(z, Wc, bc);
    k_argmax   <<<(M_ROWS / 64) * 2, 256>>>();
    k_merge    <<<(M_ROWS + 255) / 256, 256>>>();
    k_expand   <<<M_ROWS / 64, 256>>>(emb, be, out);
    k_loss     <<<M_ROWS / 8, 256>>>(emb);
    k_finalize <<<1, 256>>>(out, out_size);
}

// round 10
// speedup vs baseline: 1.1327x; 1.1327x over previous
#include <cuda_runtime.h>

#define M_ROWS 25088
#define C_IN   768
#define DIM    64
#define NE     8192

typedef unsigned long long u64;

// ---------------- scratch (device globals; no allocations allowed) ------------
__device__ float g_zf [M_ROWS * DIM];     // compressed rows, row-major (loss kernel)
__device__ float g_zfT[DIM * M_ROWS];     // compressed rows, K-major (argmax GEMM)
__device__ float g_embT[DIM * NE];        // emb transposed, K-major
__device__ float g_WeT [DIM * C_IN];      // We transposed, K-major
__device__ int   g_idx [M_ROWS];
__device__ float g_partial[M_ROWS / 8];   // per-block loss partials
__device__ float g_bv[2 * M_ROWS];        // per-n-half best value
__device__ int   g_bi[2 * M_ROWS];        // per-n-half best index

// packed f32x2 FMA (sm_103a FFMA2 — 2 fp32 MACs per fma-pipe slot)
#define FMA2(acc, a, b) asm("fma.rn.f32x2 %0, %1, %2, %0;" : "+l"(acc) : "l"(a), "l"(b))
#define BCAST2(dst, f)  asm("mov.b64 %0, {%1, %1};"        : "=l"(dst) : "f"(f))

__device__ __forceinline__ float lo32(u64 v) { return __uint_as_float((unsigned)(v)); }
__device__ __forceinline__ float hi32(u64 v) { return __uint_as_float((unsigned)(v >> 32)); }

// ---------------- 0) transpose emb and We into K-major scratch ----------------
__global__ void k_transpose(const float* __restrict__ emb, const float* __restrict__ We) {
    int i = blockIdx.x * 256 + threadIdx.x;
    if (i < NE * DIM)   { int n = i >> 6, k = i & 63; g_embT[k * NE   + n] = emb[i]; }
    if (i < C_IN * DIM) { int c = i >> 6, k = i & 63; g_WeT [k * C_IN + c] = We[i];  }
}

// ---------------- 1) compress: zf[m,d] = sum_c z[m,c]*Wc[d,c] + bc[d] ---------
__global__ __launch_bounds__(256) void k_compress(const float* __restrict__ z,
                                                  const float* __restrict__ Wc,
                                                  const float* __restrict__ bc) {
    __shared__ __align__(16) float As[32][68];   // As[k][m] (K-major)
    __shared__ __align__(16) float Bs[32][68];   // Bs[k][d]
    const int m0 = blockIdx.x * 64;
    const int tx = threadIdx.x & 15;
    const int ty = threadIdx.x >> 4;

    u64 acc[2][4];
#pragma unroll
    for (int i = 0; i < 2; i++)
#pragma unroll
        for (int j = 0; j < 4; j++) acc[i][j] = 0ull;

    for (int kk = 0; kk < C_IN; kk += 32) {
#pragma unroll
        for (int i = threadIdx.x; i < 64 * 32; i += 256) {
            int m = i >> 5, k = i & 31;
            As[k][m] = z[(size_t)(m0 + m) * C_IN + kk + k];
        }
#pragma unroll
        for (int i = threadIdx.x; i < 64 * 32; i += 256) {
            int n = i >> 5, k = i & 31;
            Bs[k][n] = Wc[(size_t)n * C_IN + kk + k];
        }
        __syncthreads();
#pragma unroll 8
        for (int k = 0; k < 32; k++) {
            ulonglong2 A = *reinterpret_cast<const ulonglong2*>(&As[k][ty * 4]);
            float4 bv = *reinterpret_cast<const float4*>(&Bs[k][tx * 4]);
            u64 b0, b1, b2, b3;
            BCAST2(b0, bv.x); BCAST2(b1, bv.y); BCAST2(b2, bv.z); BCAST2(b3, bv.w);
            FMA2(acc[0][0], A.x, b0); FMA2(acc[0][1], A.x, b1);
            FMA2(acc[0][2], A.x, b2); FMA2(acc[0][3], A.x, b3);
            FMA2(acc[1][0], A.y, b0); FMA2(acc[1][1], A.y, b1);
            FMA2(acc[1][2], A.y, b2); FMA2(acc[1][3], A.y, b3);
        }
        __syncthreads();
    }
#pragma unroll
    for (int i2 = 0; i2 < 2; i2++)
#pragma unroll
        for (int h = 0; h < 2; h++) {
            int m = m0 + ty * 4 + i2 * 2 + h;
#pragma unroll
            for (int j = 0; j < 4; j++) {
                int d = tx * 4 + j;
                float v = (h ? hi32(acc[i2][j]) : lo32(acc[i2][j])) + bc[d];
                g_zf [(size_t)m * DIM + d]    = v;
                g_zfT[(size_t)d * M_ROWS + m] = v;
            }
        }
}

// ------- 2) fused sim GEMM + argmax over one n-half --------------------------
// grid = 784 (392 m-tiles x 2 n-halves), 128 threads.
// Block tile 64m x 64n, K=64 resident. Thread tile 4m x 8n (n in f32x2 lanes).
// Es double-buffered in smem via plain LDG->STS, ONE barrier per tile:
//   iter t: write next tile into buf^1 (no reader), compute from buf, barrier.
// Static smem 52.2 KB (<= 59.9 KB proven ceiling). No cp.async.
__global__ __launch_bounds__(128) void k_argmax() {
    __shared__ __align__(16) float Zs[64][68];        // Zs[k][m]
    __shared__ __align__(16) float Es[2][64][68];     // Es[buf][k][n]

    const int tid  = threadIdx.x;
    const int bid  = blockIdx.x;
    const int m0   = (bid >> 1) * 64;
    const int half = bid & 1;
    const int nbase = half * (NE / 2);
    const int tx = tid & 7;         // 8 n-groups of 8
    const int ty = tid >> 3;        // 16 m-groups of 4

    // per-thread (k,q) slots for one Es tile (64x64 floats = 1024 float4 / 128 thr = 8 each)
    int sk[8], sq[8];
#pragma unroll
    for (int j = 0; j < 8; j++) {
        int i = tid + j * 128;
        sk[j] = i >> 4; sq[j] = (i & 15) * 4;
    }

    // load Zs (64k x 64m), K-major source: fully coalesced
#pragma unroll
    for (int i = tid; i < 64 * 16; i += 128) {
        int k = i >> 4, q = i & 15;
        *reinterpret_cast<float4*>(&Zs[k][q * 4]) =
            *reinterpret_cast<const float4*>(&g_zfT[(size_t)k * M_ROWS + m0 + q * 4]);
    }
    // preload Es tile 0 into buffer 0
#pragma unroll
    for (int j = 0; j < 8; j++) {
        *reinterpret_cast<float4*>(&Es[0][sk[j]][sq[j]]) =
            *reinterpret_cast<const float4*>(&g_embT[(size_t)sk[j] * NE + nbase + sq[j]]);
    }

    float best[4]; int bidx[4];
#pragma unroll
    for (int i = 0; i < 4; i++) { best[i] = -3.0e38f; bidx[i] = 0; }
    __syncthreads();

    const int NT = (NE / 2) / 64;   // 64 tiles
    for (int t = 0; t < NT; t++) {
        const int buf = t & 1;
        // stream next tile into the other buffer (stage regs die at the STS)
        if (t + 1 < NT) {
            const int nb = nbase + (t + 1) * 64;
#pragma unroll
            for (int j = 0; j < 8; j++)
                *reinterpret_cast<float4*>(&Es[buf ^ 1][sk[j]][sq[j]]) =
                    *reinterpret_cast<const float4*>(&g_embT[(size_t)sk[j] * NE + nb + sq[j]]);
        }

        u64 acc[4][4];   // acc[i][p]: m = ty*4+i, n-pair p (lo=even n, hi=odd n)
#pragma unroll
        for (int i = 0; i < 4; i++)
#pragma unroll
            for (int p = 0; p < 4; p++) acc[i][p] = 0ull;

#pragma unroll 8
        for (int k = 0; k < 64; k++) {
            float4 av = *reinterpret_cast<const float4*>(&Zs[k][ty * 4]);
            ulonglong2 B0 = *reinterpret_cast<const ulonglong2*>(&Es[buf][k][tx * 8]);
            ulonglong2 B1 = *reinterpret_cast<const ulonglong2*>(&Es[buf][k][tx * 8 + 4]);
            u64 a0, a1, a2, a3;
            BCAST2(a0, av.x); BCAST2(a1, av.y); BCAST2(a2, av.z); BCAST2(a3, av.w);
            FMA2(acc[0][0], a0, B0.x); FMA2(acc[0][1], a0, B0.y);
            FMA2(acc[0][2], a0, B1.x); FMA2(acc[0][3], a0, B1.y);
            FMA2(acc[1][0], a1, B0.x); FMA2(acc[1][1], a1, B0.y);
            FMA2(acc[1][2], a1, B1.x); FMA2(acc[1][3], a1, B1.y);
            FMA2(acc[2][0], a2, B0.x); FMA2(acc[2][1], a2, B0.y);
            FMA2(acc[2][2], a2, B1.x); FMA2(acc[2][3], a2, B1.y);
            FMA2(acc[3][0], a3, B0.x); FMA2(acc[3][1], a3, B0.y);
            FMA2(acc[3][2], a3, B1.x); FMA2(acc[3][3], a3, B1.y);
        }

        // argmax update: n ascending within thread; strict '>' keeps first index
        const int nt0 = nbase + t * 64 + tx * 8;
#pragma unroll
        for (int i = 0; i < 4; i++) {
#pragma unroll
            for (int p = 0; p < 4; p++) {
                int n = nt0 + p * 2;
                float vlo = lo32(acc[i][p]), vhi = hi32(acc[i][p]);
                if (vlo > best[i]) { best[i] = vlo; bidx[i] = n; }
                if (vhi > best[i]) { best[i] = vhi; bidx[i] = n + 1; }
            }
        }
        __syncthreads();   // readers of buf done; buf^1 fully written
    }

    // reduce across the 8 tx lanes (xor stays within each 8-lane group)
#pragma unroll
    for (int i = 0; i < 4; i++) {
#pragma unroll
        for (int o = 1; o < 8; o <<= 1) {
            float v  = __shfl_xor_sync(0xffffffffu, best[i], o);
            int   id = __shfl_xor_sync(0xffffffffu, bidx[i], o);
            if (v > best[i] || (v == best[i] && id < bidx[i])) { best[i] = v; bidx[i] = id; }
        }
        if (tx == 0) {
            int m = m0 + ty * 4 + i;
            g_bv[half * M_ROWS + m] = best[i];
            g_bi[half * M_ROWS + m] = bidx[i];
        }
    }
}

// ------- 2b) merge the two n-halves; tie -> lower index (= half 0) -----------
__global__ void k_merge() {
    int m = blockIdx.x * 256 + threadIdx.x;
    if (m < M_ROWS) {
        float v0 = g_bv[m], v1 = g_bv[M_ROWS + m];
        g_idx[m] = (v1 > v0) ? g_bi[M_ROWS + m] : g_bi[m];
    }
}

// ------- 3) expand: out[m,c] = sum_d emb[idx[m],d]*We[c,d] + be[c] -----------
__global__ __launch_bounds__(256) void k_expand(const float* __restrict__ emb,
                                                const float* __restrict__ be,
                                                float* __restrict__ out) {
    __shared__ __align__(16) float Zq[64][68];   // Zq[k][m] (gathered, K-major)
    __shared__ __align__(16) float Ws[64][68];   // Ws[k][c]
    const int m0 = blockIdx.x * 64;
    const int tx = threadIdx.x & 15;
    const int ty = threadIdx.x >> 4;

#pragma unroll
    for (int i = threadIdx.x; i < 64 * 16; i += 256) {
        int m = i >> 4, q = i & 15;
        float4 v = *reinterpret_cast<const float4*>(&emb[(size_t)g_idx[m0 + m] * DIM + q * 4]);
        Zq[q * 4 + 0][m] = v.x; Zq[q * 4 + 1][m] = v.y;
        Zq[q * 4 + 2][m] = v.z; Zq[q * 4 + 3][m] = v.w;
    }
    __syncthreads();

    for (int n0 = 0; n0 < C_IN; n0 += 64) {
#pragma unroll
        for (int i = threadIdx.x; i < 64 * 16; i += 256) {
            int k = i >> 4, q = i & 15;
            *reinterpret_cast<float4*>(&Ws[k][q * 4]) =
                *reinterpret_cast<const float4*>(&g_WeT[(size_t)k * C_IN + n0 + q * 4]);
        }
        __syncthreads();

        u64 acc[2][4];
#pragma unroll
        for (int i = 0; i < 2; i++)
#pragma unroll
            for (int j = 0; j < 4; j++) acc[i][j] = 0ull;

#pragma unroll 8
        for (int k = 0; k < 64; k++) {
            ulonglong2 A = *reinterpret_cast<const ulonglong2*>(&Zq[k][ty * 4]);
            float4 bv = *reinterpret_cast<const float4*>(&Ws[k][tx * 4]);
            u64 b0, b1, b2, b3;
            BCAST2(b0, bv.x); BCAST2(b1, bv.y); BCAST2(b2, bv.z); BCAST2(b3, bv.w);
            FMA2(acc[0][0], A.x, b0); FMA2(acc[0][1], A.x, b1);
            FMA2(acc[0][2], A.x, b2); FMA2(acc[0][3], A.x, b3);
            FMA2(acc[1][0], A.y, b0); FMA2(acc[1][1], A.y, b1);
            FMA2(acc[1][2], A.y, b2); FMA2(acc[1][3], A.y, b3);
        }

        float4 bev = *reinterpret_cast<const float4*>(&be[n0 + tx * 4]);
#pragma unroll
        for (int i2 = 0; i2 < 2; i2++)
#pragma unroll
            for (int h = 0; h < 2; h++) {
                int m = m0 + ty * 4 + i2 * 2 + h;
                float4 o;
                o.x = (h ? hi32(acc[i2][0]) : lo32(acc[i2][0])) + bev.x;
                o.y = (h ? hi32(acc[i2][1]) : lo32(acc[i2][1])) + bev.y;
                o.z = (h ? hi32(acc[i2][2]) : lo32(acc[i2][2])) + bev.z;
                o.w = (h ? hi32(acc[i2][3]) : lo32(acc[i2][3])) + bev.w;
                *reinterpret_cast<float4*>(&out[(size_t)m * C_IN + n0 + tx * 4]) = o;
            }
        __syncthreads();
    }
}

// ------- 4) loss partials: one warp per row, deterministic reduction ---------
__global__ void k_loss(const float* __restrict__ emb) {
    int t = blockIdx.x * 256 + threadIdx.x;
    int row = t >> 5;
    int lane = t & 31;
    const float* a = g_zf + (size_t)row * DIM;
    const float* b = emb + (size_t)g_idx[row] * DIM;
    float d = 0.f, na = 0.f, nb = 0.f;
#pragma unroll
    for (int q = 0; q < 2; q++) {
        float x = a[lane + 32 * q], y = b[lane + 32 * q];
        d = fmaf(x, y, d); na = fmaf(x, x, na); nb = fmaf(y, y, nb);
    }
#pragma unroll
    for (int o = 16; o; o >>= 1) {
        d  += __shfl_xor_sync(0xffffffffu, d, o);
        na += __shfl_xor_sync(0xffffffffu, na, o);
        nb += __shfl_xor_sync(0xffffffffu, nb, o);
    }
    __shared__ float s[8];
    if (lane == 0)
        s[threadIdx.x >> 5] = 1.0f - d / (fmaxf(sqrtf(na), 1e-8f) * fmaxf(sqrtf(nb), 1e-8f));
    __syncthreads();
    if (threadIdx.x == 0) {
        float sum = 0.f;
#pragma unroll
        for (int w = 0; w < 8; w++) sum += s[w];
        g_partial[blockIdx.x] = sum;
    }
}

// ------- 5) finalize loss: loss = 3 * mean(1 - cos) --------------------------
__global__ void k_finalize(float* __restrict__ out, int out_size) {
    __shared__ float s[256];
    float sum = 0.f;
    for (int i = threadIdx.x; i < M_ROWS / 8; i += 256) sum += g_partial[i];
    s[threadIdx.x] = sum;
    __syncthreads();
    for (int o = 128; o; o >>= 1) {
        if (threadIdx.x < o) s[threadIdx.x] += s[threadIdx.x + o];
        __syncthreads();
    }
    if (threadIdx.x == 0 && out_size > M_ROWS * C_IN)
        out[M_ROWS * C_IN] = 3.0f * s[0] / (float)M_ROWS;
}

// -----------------------------------------------------------------------------
extern "C" void kernel_launch(void* const* d_in, const int* in_sizes, int n_in,
                              void* d_out, int out_size) {
    const float *z = nullptr, *emb = nullptr, *Wc = nullptr, *bc = nullptr,
                *We = nullptr, *be = nullptr;
    for (int i = 0; i < n_in; i++) {
        int s = in_sizes[i];
        const float* p = (const float*)d_in[i];
        if      (s == M_ROWS * C_IN) z = p;
        else if (s == NE * DIM)      emb = p;
        else if (s == DIM)           bc = p;
        else if (s == C_IN)          be = p;
        else if (s == DIM * C_IN)    { if (!Wc) Wc = p; else We = p; }  // setup order: Wc then We
    }
    float* out = (float*)d_out;

    k_transpose<<<(NE * DIM + 255) / 256, 256>>>(emb, We);
    k_compress <<<M_ROWS / 64, 256>>>(z, Wc, bc);
    k_argmax   <<<(M_ROWS / 64) * 2, 128>>>();
    k_merge    <<<(M_ROWS + 255) / 256, 256>>>();
    k_expand   <<<M_ROWS / 64, 256>>>(emb, be, out);
    k_loss     <<<M_ROWS / 8, 256>>>(emb);
    k_finalize <<<1, 256>>>(out, out_size);
}

// round 11
// speedup vs baseline: 1.6068x; 1.4185x over previous
#include <cuda_runtime.h>

#define M_ROWS 25088
#define C_IN   768
#define DIM    64
#define NE     8192

typedef unsigned long long u64;

// ---------------- scratch (device globals; no allocations allowed) ------------
__device__ float g_zf [M_ROWS * DIM];     // compressed rows, row-major (loss kernel)
__device__ float g_zfT[DIM * M_ROWS];     // compressed rows, K-major (argmax GEMM)
__device__ float g_embT[DIM * NE];        // emb transposed, K-major
__device__ float g_WeT [DIM * C_IN];      // We transposed, K-major
__device__ int   g_idx [M_ROWS];
__device__ float g_partial[M_ROWS / 8];   // per-block loss partials
__device__ float g_bv[2 * M_ROWS];        // per-n-half best value
__device__ int   g_bi[2 * M_ROWS];        // per-n-half best index

// packed f32x2 FMA (sm_103a FFMA2 — 2 fp32 MACs per fma-pipe slot)
#define FMA2(acc, a, b) asm("fma.rn.f32x2 %0, %1, %2, %0;" : "+l"(acc) : "l"(a), "l"(b))
#define BCAST2(dst, f)  asm("mov.b64 %0, {%1, %1};"        : "=l"(dst) : "f"(f))

__device__ __forceinline__ float lo32(u64 v) { return __uint_as_float((unsigned)(v)); }
__device__ __forceinline__ float hi32(u64 v) { return __uint_as_float((unsigned)(v >> 32)); }

// ---------------- 0) transpose emb and We into K-major scratch ----------------
__global__ void k_transpose(const float* __restrict__ emb, const float* __restrict__ We) {
    int i = blockIdx.x * 256 + threadIdx.x;
    if (i < NE * DIM)   { int n = i >> 6, k = i & 63; g_embT[k * NE   + n] = emb[i]; }
    if (i < C_IN * DIM) { int c = i >> 6, k = i & 63; g_WeT [k * C_IN + c] = We[i];  }
}

// ---------------- dummy: zero loss partials (k_loss overwrites them) ----------
// Sole purpose: occupy launch slot 3 so ncu's fixed capture window (4th launch)
// lands on k_argmax.
__global__ void k_dummy() {
    int i = blockIdx.x * 256 + threadIdx.x;
    if (i < M_ROWS / 8) g_partial[i] = 0.0f;
}

// ---------------- 1) compress: zf[m,d] = sum_c z[m,c]*Wc[d,c] + bc[d] ---------
__global__ __launch_bounds__(256) void k_compress(const float* __restrict__ z,
                                                  const float* __restrict__ Wc,
                                                  const float* __restrict__ bc) {
    __shared__ __align__(16) float As[32][68];   // As[k][m] (K-major)
    __shared__ __align__(16) float Bs[32][68];   // Bs[k][d]
    const int m0 = blockIdx.x * 64;
    const int tx = threadIdx.x & 15;
    const int ty = threadIdx.x >> 4;

    u64 acc[2][4];
#pragma unroll
    for (int i = 0; i < 2; i++)
#pragma unroll
        for (int j = 0; j < 4; j++) acc[i][j] = 0ull;

    for (int kk = 0; kk < C_IN; kk += 32) {
#pragma unroll
        for (int i = threadIdx.x; i < 64 * 32; i += 256) {
            int m = i >> 5, k = i & 31;
            As[k][m] = z[(size_t)(m0 + m) * C_IN + kk + k];
        }
#pragma unroll
        for (int i = threadIdx.x; i < 64 * 32; i += 256) {
            int n = i >> 5, k = i & 31;
            Bs[k][n] = Wc[(size_t)n * C_IN + kk + k];
        }
        __syncthreads();
#pragma unroll 8
        for (int k = 0; k < 32; k++) {
            ulonglong2 A = *reinterpret_cast<const ulonglong2*>(&As[k][ty * 4]);
            float4 bv = *reinterpret_cast<const float4*>(&Bs[k][tx * 4]);
            u64 b0, b1, b2, b3;
            BCAST2(b0, bv.x); BCAST2(b1, bv.y); BCAST2(b2, bv.z); BCAST2(b3, bv.w);
            FMA2(acc[0][0], A.x, b0); FMA2(acc[0][1], A.x, b1);
            FMA2(acc[0][2], A.x, b2); FMA2(acc[0][3], A.x, b3);
            FMA2(acc[1][0], A.y, b0); FMA2(acc[1][1], A.y, b1);
            FMA2(acc[1][2], A.y, b2); FMA2(acc[1][3], A.y, b3);
        }
        __syncthreads();
    }
#pragma unroll
    for (int i2 = 0; i2 < 2; i2++)
#pragma unroll
        for (int h = 0; h < 2; h++) {
            int m = m0 + ty * 4 + i2 * 2 + h;
#pragma unroll
            for (int j = 0; j < 4; j++) {
                int d = tx * 4 + j;
                float v = (h ? hi32(acc[i2][j]) : lo32(acc[i2][j])) + bc[d];
                g_zf [(size_t)m * DIM + d]    = v;
                g_zfT[(size_t)d * M_ROWS + m] = v;
            }
        }
}

// ------- 2) fused sim GEMM + argmax over one n-half --------------------------
// grid = 784: blockIdx = mtile*2 + half. Tile: 64 m x 128 n inner, K=64 resident.
// Thread tile: 4 m (scalar, broadcast) x 8 n (packed f32x2 pairs).
__global__ __launch_bounds__(256) void k_argmax() {
    __shared__ __align__(16) float Zs[64][68];    // Zs[k][m]
    __shared__ __align__(16) float Es[64][132];   // Es[k][n] (128 cols + pad)
    __shared__ float red_v[64][17];
    __shared__ int   red_i[64][17];

    const int bid  = blockIdx.x;
    const int m0   = (bid >> 1) * 64;
    const int half = bid & 1;
    const int nbase = half * (NE / 2);
    const int tx = threadIdx.x & 15;
    const int ty = threadIdx.x >> 4;

    // load Zs (64k x 64m), K-major source: fully coalesced
#pragma unroll
    for (int i = threadIdx.x; i < 64 * 16; i += 256) {
        int k = i >> 4, q = i & 15;
        *reinterpret_cast<float4*>(&Zs[k][q * 4]) =
            *reinterpret_cast<const float4*>(&g_zfT[(size_t)k * M_ROWS + m0 + q * 4]);
    }
    float best[4]; int bidx[4];
#pragma unroll
    for (int i = 0; i < 4; i++) { best[i] = -3.0e38f; bidx[i] = 0; }
    __syncthreads();

    for (int n0 = 0; n0 < NE / 2; n0 += 128) {
#pragma unroll
        for (int i = threadIdx.x; i < 64 * 32; i += 256) {
            int k = i >> 5, q = i & 31;
            *reinterpret_cast<float4*>(&Es[k][q * 4]) =
                *reinterpret_cast<const float4*>(&g_embT[(size_t)k * NE + nbase + n0 + q * 4]);
        }
        __syncthreads();

        u64 acc[4][4];   // acc[i][p]: m = ty*4+i, n-pair p (lo=even n, hi=odd n)
#pragma unroll
        for (int i = 0; i < 4; i++)
#pragma unroll
            for (int p = 0; p < 4; p++) acc[i][p] = 0ull;

#pragma unroll 8
        for (int k = 0; k < 64; k++) {
            float4 av = *reinterpret_cast<const float4*>(&Zs[k][ty * 4]);
            ulonglong2 B0 = *reinterpret_cast<const ulonglong2*>(&Es[k][tx * 4]);
            ulonglong2 B1 = *reinterpret_cast<const ulonglong2*>(&Es[k][64 + tx * 4]);
            u64 a0, a1, a2, a3;
            BCAST2(a0, av.x); BCAST2(a1, av.y); BCAST2(a2, av.z); BCAST2(a3, av.w);
            FMA2(acc[0][0], a0, B0.x); FMA2(acc[0][1], a0, B0.y);
            FMA2(acc[0][2], a0, B1.x); FMA2(acc[0][3], a0, B1.y);
            FMA2(acc[1][0], a1, B0.x); FMA2(acc[1][1], a1, B0.y);
            FMA2(acc[1][2], a1, B1.x); FMA2(acc[1][3], a1, B1.y);
            FMA2(acc[2][0], a2, B0.x); FMA2(acc[2][1], a2, B0.y);
            FMA2(acc[2][2], a2, B1.x); FMA2(acc[2][3], a2, B1.y);
            FMA2(acc[3][0], a3, B0.x); FMA2(acc[3][1], a3, B0.y);
            FMA2(acc[3][2], a3, B1.x); FMA2(acc[3][3], a3, B1.y);
        }
        __syncthreads();

        // argmax update: scan n ascending per m-row; strict '>' keeps first index
        const int nt0 = nbase + n0;
#pragma unroll
        for (int i = 0; i < 4; i++) {
#pragma unroll
            for (int p = 0; p < 4; p++) {
                int n = nt0 + ((p < 2) ? (tx * 4 + p * 2) : (64 + tx * 4 + (p - 2) * 2));
                float vlo = lo32(acc[i][p]), vhi = hi32(acc[i][p]);
                if (vlo > best[i]) { best[i] = vlo; bidx[i] = n; }
                if (vhi > best[i]) { best[i] = vhi; bidx[i] = n + 1; }
            }
        }
    }

    // cross-tx reduction per m row
#pragma unroll
    for (int i = 0; i < 4; i++) {
        red_v[ty * 4 + i][tx] = best[i];
        red_i[ty * 4 + i][tx] = bidx[i];
    }
    __syncthreads();
    if (threadIdx.x < 64) {
        int m = threadIdx.x;
        float bv = red_v[m][0]; int bi = red_i[m][0];
#pragma unroll
        for (int t = 1; t < 16; t++) {
            float v = red_v[m][t]; int id = red_i[m][t];
            if (v > bv || (v == bv && id < bi)) { bv = v; bi = id; }
        }
        g_bv[half * M_ROWS + m0 + m] = bv;
        g_bi[half * M_ROWS + m0 + m] = bi;
    }
}

// ------- 2b) merge the two n-halves; tie -> lower index (= half 0) -----------
__global__ void k_merge() {
    int m = blockIdx.x * 256 + threadIdx.x;
    if (m < M_ROWS) {
        float v0 = g_bv[m], v1 = g_bv[M_ROWS + m];
        g_idx[m] = (v1 > v0) ? g_bi[M_ROWS + m] : g_bi[m];
    }
}

// ------- 3) expand: out[m,c] = sum_d emb[idx[m],d]*We[c,d] + be[c] -----------
__global__ __launch_bounds__(256) void k_expand(const float* __restrict__ emb,
                                                const float* __restrict__ be,
                                                float* __restrict__ out) {
    __shared__ __align__(16) float Zq[64][68];   // Zq[k][m] (gathered, K-major)
    __shared__ __align__(16) float Ws[64][68];   // Ws[k][c]
    const int m0 = blockIdx.x * 64;
    const int tx = threadIdx.x & 15;
    const int ty = threadIdx.x >> 4;

#pragma unroll
    for (int i = threadIdx.x; i < 64 * 16; i += 256) {
        int m = i >> 4, q = i & 15;
        float4 v = *reinterpret_cast<const float4*>(&emb[(size_t)g_idx[m0 + m] * DIM + q * 4]);
        Zq[q * 4 + 0][m] = v.x; Zq[q * 4 + 1][m] = v.y;
        Zq[q * 4 + 2][m] = v.z; Zq[q * 4 + 3][m] = v.w;
    }
    __syncthreads();

    for (int n0 = 0; n0 < C_IN; n0 += 64) {
#pragma unroll
        for (int i = threadIdx.x; i < 64 * 16; i += 256) {
            int k = i >> 4, q = i & 15;
            *reinterpret_cast<float4*>(&Ws[k][q * 4]) =
                *reinterpret_cast<const float4*>(&g_WeT[(size_t)k * C_IN + n0 + q * 4]);
        }
        __syncthreads();

        u64 acc[2][4];
#pragma unroll
        for (int i = 0; i < 2; i++)
#pragma unroll
            for (int j = 0; j < 4; j++) acc[i][j] = 0ull;

#pragma unroll 8
        for (int k = 0; k < 64; k++) {
            ulonglong2 A = *reinterpret_cast<const ulonglong2*>(&Zq[k][ty * 4]);
            float4 bv = *reinterpret_cast<const float4*>(&Ws[k][tx * 4]);
            u64 b0, b1, b2, b3;
            BCAST2(b0, bv.x); BCAST2(b1, bv.y); BCAST2(b2, bv.z); BCAST2(b3, bv.w);
            FMA2(acc[0][0], A.x, b0); FMA2(acc[0][1], A.x, b1);
            FMA2(acc[0][2], A.x, b2); FMA2(acc[0][3], A.x, b3);
            FMA2(acc[1][0], A.y, b0); FMA2(acc[1][1], A.y, b1);
            FMA2(acc[1][2], A.y, b2); FMA2(acc[1][3], A.y, b3);
        }

        float4 bev = *reinterpret_cast<const float4*>(&be[n0 + tx * 4]);
#pragma unroll
        for (int i2 = 0; i2 < 2; i2++)
#pragma unroll
            for (int h = 0; h < 2; h++) {
                int m = m0 + ty * 4 + i2 * 2 + h;
                float4 o;
                o.x = (h ? hi32(acc[i2][0]) : lo32(acc[i2][0])) + bev.x;
                o.y = (h ? hi32(acc[i2][1]) : lo32(acc[i2][1])) + bev.y;
                o.z = (h ? hi32(acc[i2][2]) : lo32(acc[i2][2])) + bev.z;
                o.w = (h ? hi32(acc[i2][3]) : lo32(acc[i2][3])) + bev.w;
                *reinterpret_cast<float4*>(&out[(size_t)m * C_IN + n0 + tx * 4]) = o;
            }
        __syncthreads();
    }
}

// ------- 4) loss partials: one warp per row, deterministic reduction ---------
__global__ void k_loss(const float* __restrict__ emb) {
    int t = blockIdx.x * 256 + threadIdx.x;
    int row = t >> 5;
    int lane = t & 31;
    const float* a = g_zf + (size_t)row * DIM;
    const float* b = emb + (size_t)g_idx[row] * DIM;
    float d = 0.f, na = 0.f, nb = 0.f;
#pragma unroll
    for (int q = 0; q < 2; q++) {
        float x = a[lane + 32 * q], y = b[lane + 32 * q];
        d = fmaf(x, y, d); na = fmaf(x, x, na); nb = fmaf(y, y, nb);
    }
#pragma unroll
    for (int o = 16; o; o >>= 1) {
        d  += __shfl_xor_sync(0xffffffffu, d, o);
        na += __shfl_xor_sync(0xffffffffu, na, o);
        nb += __shfl_xor_sync(0xffffffffu, nb, o);
    }
    __shared__ float s[8];
    if (lane == 0)
        s[threadIdx.x >> 5] = 1.0f - d / (fmaxf(sqrtf(na), 1e-8f) * fmaxf(sqrtf(nb), 1e-8f));
    __syncthreads();
    if (threadIdx.x == 0) {
        float sum = 0.f;
#pragma unroll
        for (int w = 0; w < 8; w++) sum += s[w];
        g_partial[blockIdx.x] = sum;
    }
}

// ------- 5) finalize loss: loss = 3 * mean(1 - cos) --------------------------
__global__ void k_finalize(float* __restrict__ out, int out_size) {
    __shared__ float s[256];
    float sum = 0.f;
    for (int i = threadIdx.x; i < M_ROWS / 8; i += 256) sum += g_partial[i];
    s[threadIdx.x] = sum;
    __syncthreads();
    for (int o = 128; o; o >>= 1) {
        if (threadIdx.x < o) s[threadIdx.x] += s[threadIdx.x + o];
        __syncthreads();
    }
    if (threadIdx.x == 0 && out_size > M_ROWS * C_IN)
        out[M_ROWS * C_IN] = 3.0f * s[0] / (float)M_ROWS;
}

// -----------------------------------------------------------------------------
extern "C" void kernel_launch(void* const* d_in, const int* in_sizes, int n_in,
                              void* d_out, int out_size) {
    const float *z = nullptr, *emb = nullptr, *Wc = nullptr, *bc = nullptr,
                *We = nullptr, *be = nullptr;
    for (int i = 0; i < n_in; i++) {
        int s = in_sizes[i];
        const float* p = (const float*)d_in[i];
        if      (s == M_ROWS * C_IN) z = p;
        else if (s == NE * DIM)      emb = p;
        else if (s == DIM)           bc = p;
        else if (s == C_IN)          be = p;
        else if (s == DIM * C_IN)    { if (!Wc) Wc = p; else We = p; }  // setup order: Wc then We
    }
    float* out = (float*)d_out;

    k_transpose<<<(NE * DIM + 255) / 256, 256>>>(emb, We);          // launch 1
    k_compress <<<M_ROWS / 64, 256>>>(z, Wc, bc);                    // launch 2
    k_dummy    <<<(M_ROWS / 8 + 255) / 256, 256>>>();                // launch 3 (slot shim)
    k_argmax   <<<(M_ROWS / 64) * 2, 256>>>();                       // launch 4 -> ncu target
    k_merge    <<<(M_ROWS + 255) / 256, 256>>>();
    k_expand   <<<M_ROWS / 64, 256>>>(emb, be, out);
    k_loss     <<<M_ROWS / 8, 256>>>(emb);
    k_finalize <<<1, 256>>>(out, out_size);
}

// round 13
// speedup vs baseline: 1.6180x; 1.0070x over previous
#include <cuda_runtime.h>

#define M_ROWS 25088
#define C_IN   768
#define DIM    64
#define NE     8192

typedef unsigned long long u64;

// ---------------- scratch (device globals; no allocations allowed) ------------
__device__ float g_zf [M_ROWS * DIM];     // compressed rows, row-major (loss kernel)
__device__ float g_zfT[DIM * M_ROWS];     // compressed rows, K-major (argmax GEMM)
__device__ float g_embT[DIM * NE];        // emb transposed, K-major
__device__ float g_WeT [DIM * C_IN];      // We transposed, K-major
__device__ int   g_idx [M_ROWS];
__device__ float g_partial[M_ROWS / 8];   // per-block loss partials
__device__ float g_bv[2 * M_ROWS];        // per-n-half best value
__device__ int   g_bi[2 * M_ROWS];        // per-n-half best index

// packed f32x2 FMA (sm_103a FFMA2 — 2 fp32 MACs per fma-pipe slot)
#define FMA2(acc, a, b) asm("fma.rn.f32x2 %0, %1, %2, %0;" : "+l"(acc) : "l"(a), "l"(b))
#define BCAST2(dst, f)  asm("mov.b64 %0, {%1, %1};"        : "=l"(dst) : "f"(f))

__device__ __forceinline__ float lo32(u64 v) { return __uint_as_float((unsigned)(v)); }
__device__ __forceinline__ float hi32(u64 v) { return __uint_as_float((unsigned)(v >> 32)); }

// ---------------- 0) transpose emb and We into K-major scratch ----------------
__global__ void k_transpose(const float* __restrict__ emb, const float* __restrict__ We) {
    int i = blockIdx.x * 256 + threadIdx.x;
    if (i < NE * DIM)   { int n = i >> 6, k = i & 63; g_embT[k * NE   + n] = emb[i]; }
    if (i < C_IN * DIM) { int c = i >> 6, k = i & 63; g_WeT [k * C_IN + c] = We[i];  }
}

// ---------------- dummy: zero loss partials (k_loss overwrites them) ----------
// Occupies launch slot 3 so ncu's fixed capture window (4th launch) = k_argmax.
__global__ void k_dummy() {
    int i = blockIdx.x * 256 + threadIdx.x;
    if (i < M_ROWS / 8) g_partial[i] = 0.0f;
}

// ---------------- 1) compress: zf[m,d] = sum_c z[m,c]*Wc[d,c] + bc[d] ---------
__global__ __launch_bounds__(256) void k_compress(const float* __restrict__ z,
                                                  const float* __restrict__ Wc,
                                                  const float* __restrict__ bc) {
    __shared__ __align__(16) float As[32][68];   // As[k][m] (K-major)
    __shared__ __align__(16) float Bs[32][68];   // Bs[k][d]
    const int m0 = blockIdx.x * 64;
    const int tx = threadIdx.x & 15;
    const int ty = threadIdx.x >> 4;

    u64 acc[2][4];
#pragma unroll
    for (int i = 0; i < 2; i++)
#pragma unroll
        for (int j = 0; j < 4; j++) acc[i][j] = 0ull;

    for (int kk = 0; kk < C_IN; kk += 32) {
#pragma unroll
        for (int i = threadIdx.x; i < 64 * 32; i += 256) {
            int m = i >> 5, k = i & 31;
            As[k][m] = z[(size_t)(m0 + m) * C_IN + kk + k];
        }
#pragma unroll
        for (int i = threadIdx.x; i < 64 * 32; i += 256) {
            int n = i >> 5, k = i & 31;
            Bs[k][n] = Wc[(size_t)n * C_IN + kk + k];
        }
        __syncthreads();
#pragma unroll 8
        for (int k = 0; k < 32; k++) {
            ulonglong2 A = *reinterpret_cast<const ulonglong2*>(&As[k][ty * 4]);
            float4 bv = *reinterpret_cast<const float4*>(&Bs[k][tx * 4]);
            u64 b0, b1, b2, b3;
            BCAST2(b0, bv.x); BCAST2(b1, bv.y); BCAST2(b2, bv.z); BCAST2(b3, bv.w);
            FMA2(acc[0][0], A.x, b0); FMA2(acc[0][1], A.x, b1);
            FMA2(acc[0][2], A.x, b2); FMA2(acc[0][3], A.x, b3);
            FMA2(acc[1][0], A.y, b0); FMA2(acc[1][1], A.y, b1);
            FMA2(acc[1][2], A.y, b2); FMA2(acc[1][3], A.y, b3);
        }
        __syncthreads();
    }
#pragma unroll
    for (int i2 = 0; i2 < 2; i2++)
#pragma unroll
        for (int h = 0; h < 2; h++) {
            int m = m0 + ty * 4 + i2 * 2 + h;
#pragma unroll
            for (int j = 0; j < 4; j++) {
                int d = tx * 4 + j;
                float v = (h ? hi32(acc[i2][j]) : lo32(acc[i2][j])) + bc[d];
                g_zf [(size_t)m * DIM + d]    = v;
                g_zfT[(size_t)d * M_ROWS + m] = v;
            }
        }
}

// ------- 2) fused sim GEMM + argmax over one n-half --------------------------
// grid = 784 (392 m-tiles x 2 n-halves), 128 threads.
// Block tile 64m x 128n, K=64 resident. Thread tile 8m x 8n (n in f32x2 lanes):
// per k-step 4 LDS.128 + 8 BCAST + 32 FFMA2 -> fma-pipe-bound, not L1-bound.
// Static smem 50.0 KB. Plain single-buffer loop (proven structure), no cp.async.
__global__ __launch_bounds__(128) void k_argmax() {
    __shared__ __align__(16) float Zs[64][68];    // Zs[k][m]
    __shared__ __align__(16) float Es[64][132];   // Es[k][n] (128 cols + pad)

    const int tid  = threadIdx.x;
    const int bid  = blockIdx.x;
    const int m0   = (bid >> 1) * 64;
    const int half = bid & 1;
    const int nbase = half * (NE / 2);
    const int tx = tid & 15;        // 16 n-groups of 8 (two 64-wide halves)
    const int ty = tid >> 4;        // 8 m-groups of 8

    // load Zs (64k x 64m), K-major source: fully coalesced
#pragma unroll
    for (int i = tid; i < 64 * 16; i += 128) {
        int k = i >> 4, q = i & 15;
        *reinterpret_cast<float4*>(&Zs[k][q * 4]) =
            *reinterpret_cast<const float4*>(&g_zfT[(size_t)k * M_ROWS + m0 + q * 4]);
    }
    float best[8]; int bidx[8];
#pragma unroll
    for (int i = 0; i < 8; i++) { best[i] = -3.0e38f; bidx[i] = 0; }
    __syncthreads();

    for (int n0 = 0; n0 < NE / 2; n0 += 128) {
#pragma unroll
        for (int i = tid; i < 64 * 32; i += 128) {
            int k = i >> 5, q = i & 31;
            *reinterpret_cast<float4*>(&Es[k][q * 4]) =
                *reinterpret_cast<const float4*>(&g_embT[(size_t)k * NE + nbase + n0 + q * 4]);
        }
        __syncthreads();

        u64 acc[8][4];   // acc[i][p]: m = ty*8+i, n-pair p (lo=even n, hi=odd n)
#pragma unroll
        for (int i = 0; i < 8; i++)
#pragma unroll
            for (int p = 0; p < 4; p++) acc[i][p] = 0ull;

#pragma unroll 4
        for (int k = 0; k < 64; k++) {
            float4 a0v = *reinterpret_cast<const float4*>(&Zs[k][ty * 8]);
            float4 a1v = *reinterpret_cast<const float4*>(&Zs[k][ty * 8 + 4]);
            ulonglong2 B0 = *reinterpret_cast<const ulonglong2*>(&Es[k][tx * 4]);
            ulonglong2 B1 = *reinterpret_cast<const ulonglong2*>(&Es[k][64 + tx * 4]);
            u64 av[8];
            BCAST2(av[0], a0v.x); BCAST2(av[1], a0v.y);
            BCAST2(av[2], a0v.z); BCAST2(av[3], a0v.w);
            BCAST2(av[4], a1v.x); BCAST2(av[5], a1v.y);
            BCAST2(av[6], a1v.z); BCAST2(av[7], a1v.w);
#pragma unroll
            for (int i = 0; i < 8; i++) {
                FMA2(acc[i][0], av[i], B0.x);
                FMA2(acc[i][1], av[i], B0.y);
                FMA2(acc[i][2], av[i], B1.x);
                FMA2(acc[i][3], av[i], B1.y);
            }
        }
        __syncthreads();

        // argmax update: scan n ascending per m-row; strict '>' keeps first index
        const int nt0 = nbase + n0;
#pragma unroll
        for (int i = 0; i < 8; i++) {
#pragma unroll
            for (int p = 0; p < 4; p++) {
                int n = nt0 + ((p < 2) ? (tx * 4 + p * 2) : (64 + tx * 4 + (p - 2) * 2));
                float vlo = lo32(acc[i][p]), vhi = hi32(acc[i][p]);
                if (vlo > best[i]) { best[i] = vlo; bidx[i] = n; }
                if (vhi > best[i]) { best[i] = vhi; bidx[i] = n + 1; }
            }
        }
    }

    // reduce across the 16 tx lanes (xor o<16 stays inside each 16-lane group)
#pragma unroll
    for (int i = 0; i < 8; i++) {
#pragma unroll
        for (int o = 1; o < 16; o <<= 1) {
            float v  = __shfl_xor_sync(0xffffffffu, best[i], o);
            int   id = __shfl_xor_sync(0xffffffffu, bidx[i], o);
            if (v > best[i] || (v == best[i] && id < bidx[i])) { best[i] = v; bidx[i] = id; }
        }
        if (tx == 0) {
            int m = m0 + ty * 8 + i;
            g_bv[half * M_ROWS + m] = best[i];
            g_bi[half * M_ROWS + m] = bidx[i];
        }
    }
}

// ------- 2b) merge the two n-halves; tie -> lower index (= half 0) -----------
__global__ void k_merge() {
    int m = blockIdx.x * 256 + threadIdx.x;
    if (m < M_ROWS) {
        float v0 = g_bv[m], v1 = g_bv[M_ROWS + m];
        g_idx[m] = (v1 > v0) ? g_bi[M_ROWS + m] : g_bi[m];
    }
}

// ------- 3) expand: out[m,c] = sum_d emb[idx[m],d]*We[c,d] + be[c] -----------
__global__ __launch_bounds__(256) void k_expand(const float* __restrict__ emb,
                                                const float* __restrict__ be,
                                                float* __restrict__ out) {
    __shared__ __align__(16) float Zq[64][68];   // Zq[k][m] (gathered, K-major)
    __shared__ __align__(16) float Ws[64][68];   // Ws[k][c]
    const int m0 = blockIdx.x * 64;
    const int tx = threadIdx.x & 15;
    const int ty = threadIdx.x >> 4;

#pragma unroll
    for (int i = threadIdx.x; i < 64 * 16; i += 256) {
        int m = i >> 4, q = i & 15;
        float4 v = *reinterpret_cast<const float4*>(&emb[(size_t)g_idx[m0 + m] * DIM + q * 4]);
        Zq[q * 4 + 0][m] = v.x; Zq[q * 4 + 1][m] = v.y;
        Zq[q * 4 + 2][m] = v.z; Zq[q * 4 + 3][m] = v.w;
    }
    __syncthreads();

    for (int n0 = 0; n0 < C_IN; n0 += 64) {
#pragma unroll
        for (int i = threadIdx.x; i < 64 * 16; i += 256) {
            int k = i >> 4, q = i & 15;
            *reinterpret_cast<float4*>(&Ws[k][q * 4]) =
                *reinterpret_cast<const float4*>(&g_WeT[(size_t)k * C_IN + n0 + q * 4]);
        }
        __syncthreads();

        u64 acc[2][4];
#pragma unroll
        for (int i = 0; i < 2; i++)
#pragma unroll
            for (int j = 0; j < 4; j++) acc[i][j] = 0ull;

#pragma unroll 8
        for (int k = 0; k < 64; k++) {
            ulonglong2 A = *reinterpret_cast<const ulonglong2*>(&Zq[k][ty * 4]);
            float4 bv = *reinterpret_cast<const float4*>(&Ws[k][tx * 4]);
            u64 b0, b1, b2, b3;
            BCAST2(b0, bv.x); BCAST2(b1, bv.y); BCAST2(b2, bv.z); BCAST2(b3, bv.w);
            FMA2(acc[0][0], A.x, b0); FMA2(acc[0][1], A.x, b1);
            FMA2(acc[0][2], A.x, b2); FMA2(acc[0][3], A.x, b3);
            FMA2(acc[1][0], A.y, b0); FMA2(acc[1][1], A.y, b1);
            FMA2(acc[1][2], A.y, b2); FMA2(acc[1][3], A.y, b3);
        }

        float4 bev = *reinterpret_cast<const float4*>(&be[n0 + tx * 4]);
#pragma unroll
        for (int i2 = 0; i2 < 2; i2++)
#pragma unroll
            for (int h = 0; h < 2; h++) {
                int m = m0 + ty * 4 + i2 * 2 + h;
                float4 o;
                o.x = (h ? hi32(acc[i2][0]) : lo32(acc[i2][0])) + bev.x;
                o.y = (h ? hi32(acc[i2][1]) : lo32(acc[i2][1])) + bev.y;
                o.z = (h ? hi32(acc[i2][2]) : lo32(acc[i2][2])) + bev.z;
                o.w = (h ? hi32(acc[i2][3]) : lo32(acc[i2][3])) + bev.w;
                *reinterpret_cast<float4*>(&out[(size_t)m * C_IN + n0 + tx * 4]) = o;
            }
        __syncthreads();
    }
}

// ------- 4) loss partials: one warp per row, deterministic reduction ---------
__global__ void k_loss(const float* __restrict__ emb) {
    int t = blockIdx.x * 256 + threadIdx.x;
    int row = t >> 5;
    int lane = t & 31;
    const float* a = g_zf + (size_t)row * DIM;
    const float* b = emb + (size_t)g_idx[row] * DIM;
    float d = 0.f, na = 0.f, nb = 0.f;
#pragma unroll
    for (int q = 0; q < 2; q++) {
        float x = a[lane + 32 * q], y = b[lane + 32 * q];
        d = fmaf(x, y, d); na = fmaf(x, x, na); nb = fmaf(y, y, nb);
    }
#pragma unroll
    for (int o = 16; o; o >>= 1) {
        d  += __shfl_xor_sync(0xffffffffu, d, o);
        na += __shfl_xor_sync(0xffffffffu, na, o);
        nb += __shfl_xor_sync(0xffffffffu, nb, o);
    }
    __shared__ float s[8];
    if (lane == 0)
        s[threadIdx.x >> 5] = 1.0f - d / (fmaxf(sqrtf(na), 1e-8f) * fmaxf(sqrtf(nb), 1e-8f));
    __syncthreads();
    if (threadIdx.x == 0) {
        float sum = 0.f;
#pragma unroll
        for (int w = 0; w < 8; w++) sum += s[w];
        g_partial[blockIdx.x] = sum;
    }
}

// ------- 5) finalize loss: loss = 3 * mean(1 - cos) --------------------------
__global__ void k_finalize(float* __restrict__ out, int out_size) {
    __shared__ float s[256];
    float sum = 0.f;
    for (int i = threadIdx.x; i < M_ROWS / 8; i += 256) sum += g_partial[i];
    s[threadIdx.x] = sum;
    __syncthreads();
    for (int o = 128; o; o >>= 1) {
        if (threadIdx.x < o) s[threadIdx.x] += s[threadIdx.x + o];
        __syncthreads();
    }
    if (threadIdx.x == 0 && out_size > M_ROWS * C_IN)
        out[M_ROWS * C_IN] = 3.0f * s[0] / (float)M_ROWS;
}

// -----------------------------------------------------------------------------
extern "C" void kernel_launch(void* const* d_in, const int* in_sizes, int n_in,
                              void* d_out, int out_size) {
    const float *z = nullptr, *emb = nullptr, *Wc = nullptr, *bc = nullptr,
                *We = nullptr, *be = nullptr;
    for (int i = 0; i < n_in; i++) {
        int s = in_sizes[i];
        const float* p = (const float*)d_in[i];
        if      (s == M_ROWS * C_IN) z = p;
        else if (s == NE * DIM)      emb = p;
        else if (s == DIM)           bc = p;
        else if (s == C_IN)          be = p;
        else if (s == DIM * C_IN)    { if (!Wc) Wc = p; else We = p; }  // setup order: Wc then We
    }
    float* out = (float*)d_out;

    k_transpose<<<(NE * DIM + 255) / 256, 256>>>(emb, We);          // launch 1
    k_compress <<<M_ROWS / 64, 256>>>(z, Wc, bc);                    // launch 2
    k_dummy    <<<(M_ROWS / 8 + 255) / 256, 256>>>();                // launch 3 (slot shim)
    k_argmax   <<<(M_ROWS / 64) * 2, 128>>>();                       // launch 4 -> ncu target
    k_merge    <<<(M_ROWS + 255) / 256, 256>>>();
    k_expand   <<<M_ROWS / 64, 256>>>(emb, be, out);
    k_loss     <<<M_ROWS / 8, 256>>>(emb);
    k_finalize <<<1, 256>>>(out, out_size);
}